// round 9
// baseline (speedup 1.0000x reference)
#include <cuda_runtime.h>
#include <cuda_fp16.h>
#include <math.h>
#include <stdint.h>

// Problem shape (fixed by the dataset)
#define NB      4
#define SEQ     4096
#define DDIM    1024
#define HDIM    128
#define BSTOT   (NB * SEQ)          // 16384 rows
#define NQT     64                  // q-tiles per batch (SEQ/64)

// ---------------- scratch (no cudaMalloc allowed) ----------------
__device__ __half g_Xh[BSTOT * DDIM];       // fp16 X
__device__ __half g_Wh[3 * DDIM * HDIM];    // fp16 Wq|Wk|Wv
__device__ __half g_Qh[BSTOT * HDIM];       // fp16 Q (pre-scaled by 1/sqrt(128))
__device__ __half g_Kh[BSTOT * HDIM];
__device__ __half g_Vh[BSTOT * HDIM];
// split-K partials: [b][qtile][half]{ o:64x128, m:64, l:64 }
__device__ float g_Po[NB * NQT * 2 * 64 * HDIM];
__device__ float g_Pm[NB * NQT * 2 * 64];
__device__ float g_Pl[NB * NQT * 2 * 64];

// ------------------- helpers -------------------
// fp16: D += A(16x16, row) * B(16x8, col), fp32 accum
__device__ __forceinline__ void mma16(float* c, const uint32_t* a, const uint32_t* b) {
    asm volatile("mma.sync.aligned.m16n8k16.row.col.f32.f16.f16.f32 "
        "{%0,%1,%2,%3}, {%4,%5,%6,%7}, {%8,%9}, {%0,%1,%2,%3};"
        : "+f"(c[0]), "+f"(c[1]), "+f"(c[2]), "+f"(c[3])
        : "r"(a[0]), "r"(a[1]), "r"(a[2]), "r"(a[3]), "r"(b[0]), "r"(b[1]));
}
__device__ __forceinline__ void ldsm4(uint32_t& r0, uint32_t& r1, uint32_t& r2, uint32_t& r3,
                                      uint32_t addr) {
    asm volatile("ldmatrix.sync.aligned.m8n8.x4.shared.b16 {%0,%1,%2,%3}, [%4];"
        : "=r"(r0), "=r"(r1), "=r"(r2), "=r"(r3) : "r"(addr));
}
__device__ __forceinline__ void ldsm4t(uint32_t& r0, uint32_t& r1, uint32_t& r2, uint32_t& r3,
                                       uint32_t addr) {
    asm volatile("ldmatrix.sync.aligned.m8n8.x4.trans.shared.b16 {%0,%1,%2,%3}, [%4];"
        : "=r"(r0), "=r"(r1), "=r"(r2), "=r"(r3) : "r"(addr));
}
// pack two f32 -> f16x2 (lo = first element)
__device__ __forceinline__ uint32_t ph2(float lo, float hi) {
    uint32_t r; asm("cvt.rn.f16x2.f32 %0, %1, %2;" : "=r"(r) : "f"(hi), "f"(lo)); return r;
}
__device__ __forceinline__ uint32_t smaddr(const void* p) {
    return (uint32_t)__cvta_generic_to_shared(p);
}
__device__ __forceinline__ void cp16(uint32_t s, const void* g) {
    asm volatile("cp.async.ca.shared.global [%0], [%1], 16;" :: "r"(s), "l"(g));
}
__device__ __forceinline__ void cp_commit() {
    asm volatile("cp.async.commit_group;");
}
template <int N>
__device__ __forceinline__ void cp_wait() {
    asm volatile("cp.async.wait_group %0;" :: "n"(N));
}

// ======================= fp32 -> fp16 converts =========================
__global__ __launch_bounds__(256) void convert_X_kernel(const float* __restrict__ X)
{
    size_t i = ((size_t)blockIdx.x * 256 + threadIdx.x) * 8;
    float4 a = *(const float4*)(X + i);
    float4 b = *(const float4*)(X + i + 4);
    uint4 o;
    o.x = ph2(a.x, a.y); o.y = ph2(a.z, a.w);
    o.z = ph2(b.x, b.y); o.w = ph2(b.z, b.w);
    *(uint4*)(g_Xh + i) = o;
}
__global__ __launch_bounds__(256) void convert_W_kernel(
    const float* __restrict__ Wq, const float* __restrict__ Wk,
    const float* __restrict__ Wv)
{
    const float* W = (blockIdx.y == 0) ? Wq : ((blockIdx.y == 1) ? Wk : Wv);
    size_t i = ((size_t)blockIdx.x * 256 + threadIdx.x) * 8;
    float4 a = *(const float4*)(W + i);
    float4 b = *(const float4*)(W + i + 4);
    uint4 o;
    o.x = ph2(a.x, a.y); o.y = ph2(a.z, a.w);
    o.z = ph2(b.x, b.y); o.w = ph2(b.z, b.w);
    *(uint4*)(g_Wh + (size_t)blockIdx.y * DDIM * HDIM + i) = o;
}

// ======================= QKV projection (fp16) =========================
#define PXS 40
#define PWS 136
#define PROJ_SMEM ((2 * 128 * PXS + 2 * 32 * PWS) * 2)   // 37888 B

__global__ __launch_bounds__(256, 2) void proj_kernel()
{
    const int mat = blockIdx.y;
    const __half* Xg = g_Xh;
    const __half* Wg = g_Wh + (size_t)mat * DDIM * HDIM;
    __half*      Outh = (mat == 0) ? g_Qh : ((mat == 1) ? g_Kh : g_Vh);

    extern __shared__ __half psm[];
    __half* Xb = psm;                      // [2][128*PXS]
    __half* Wb = psm + 2 * 128 * PXS;      // [2][32*PWS]

    const int tid  = threadIdx.x;
    const int warp = tid >> 5, lane = tid & 31;
    const int g = lane >> 2, tig = lane & 3;
    const int wm = warp & 3;
    const int wn = warp >> 2;
    const int row0 = blockIdx.x * 128;

    auto issue_stage = [&](int k0, int s) {
        __half* Xd = Xb + s * 128 * PXS;
        __half* Wd = Wb + s * 32 * PWS;
#pragma unroll
        for (int c = tid; c < 512; c += 256) {
            int r = c >> 2, c8 = c & 3;
            cp16(smaddr(Xd + r * PXS + c8 * 8),
                 Xg + (size_t)(row0 + r) * DDIM + k0 + c8 * 8);
        }
#pragma unroll
        for (int c = tid; c < 512; c += 256) {
            int r = c >> 4, c8 = c & 15;
            cp16(smaddr(Wd + r * PWS + c8 * 8),
                 Wg + (size_t)(k0 + r) * HDIM + c8 * 8);
        }
        cp_commit();
    };

    float acc[2][8][4];
#pragma unroll
    for (int mi = 0; mi < 2; mi++)
#pragma unroll
        for (int ni = 0; ni < 8; ni++)
#pragma unroll
            for (int j = 0; j < 4; j++) acc[mi][ni][j] = 0.f;

    issue_stage(0, 0);

    const int a_off = (lane & 15) * PXS + (lane >> 4) * 8;
    const int b_off = lane * PWS;

    for (int ki = 0; ki < 32; ki++) {
        if (ki < 31) { issue_stage((ki + 1) * 32, (ki + 1) & 1); cp_wait<1>(); }
        else         { cp_wait<0>(); }
        __syncthreads();

        const uint32_t XsA = smaddr(Xb + (ki & 1) * 128 * PXS);
        const uint32_t WsA = smaddr(Wb + (ki & 1) * 32 * PWS);

        uint32_t a[2][2][4];
#pragma unroll
        for (int mi = 0; mi < 2; mi++)
#pragma unroll
            for (int kc = 0; kc < 2; kc++) {
                uint32_t addr = XsA + (uint32_t)((wm * 32 + mi * 16) * PXS + kc * 16 + a_off) * 2;
                ldsm4(a[mi][kc][0], a[mi][kc][1], a[mi][kc][2], a[mi][kc][3], addr);
            }
#pragma unroll
        for (int ni = 0; ni < 8; ni++) {
            uint32_t r0, r1, r2, r3;
            uint32_t addr = WsA + (uint32_t)(b_off + wn * 64 + ni * 8) * 2;
            ldsm4t(r0, r1, r2, r3, addr);
            uint32_t b01[2] = {r0, r1}, b23[2] = {r2, r3};
#pragma unroll
            for (int mi = 0; mi < 2; mi++) {
                mma16(acc[mi][ni], a[mi][0], b01);
                mma16(acc[mi][ni], a[mi][1], b23);
            }
        }
        __syncthreads();
    }

    const float osc = (mat == 0) ? 0.088388347648318447f : 1.0f;
#pragma unroll
    for (int mi = 0; mi < 2; mi++) {
        const int r = row0 + wm * 32 + mi * 16 + g;
#pragma unroll
        for (int ni = 0; ni < 8; ni++) {
            const int c = wn * 64 + ni * 8 + 2 * tig;
            *(uint32_t*)(Outh + (size_t)r       * HDIM + c) =
                ph2(acc[mi][ni][0] * osc, acc[mi][ni][1] * osc);
            *(uint32_t*)(Outh + (size_t)(r + 8) * HDIM + c) =
                ph2(acc[mi][ni][2] * osc, acc[mi][ni][3] * osc);
        }
    }
}

// ======================= flash attention (split-K) ========================
// grid (128, NB): bx -> qtile = 63-(bx>>1), half = bx&1.
// 128 threads = 4 warps; Q tile in smem (re-fetched via ldmatrix per step);
// K double-buffered, V single-buffered; target 3 CTAs/SM.
#define HS 136                       // half-stride per smem row (272 B)
#define ATT_SMEM (4 * 64 * HS * 2)   // Q + 2 K bufs + 1 V buf = 69632 B

__global__ __launch_bounds__(128, 3) void attn_kernel()
{
    extern __shared__ __half hsm[];
    __half* Qs = hsm;                  // [64*HS]
    __half* Kb = hsm + 64 * HS;        // [2][64*HS]
    __half* Vb = hsm + 3 * 64 * HS;    // [64*HS]

    const int tid  = threadIdx.x;
    const int warp = tid >> 5, lane = tid & 31;
    const int g = lane >> 2, tig = lane & 3;
    const int rb = warp * 16;
    const int b  = blockIdx.y;

    const __half* Q = g_Qh + (size_t)b * SEQ * HDIM;
    const __half* K = g_Kh + (size_t)b * SEQ * HDIM;
    const __half* V = g_Vh + (size_t)b * SEQ * HDIM;

    const int qtile = 63 - ((int)blockIdx.x >> 1);   // longest first
    const int half  = (int)blockIdx.x & 1;
    const int qbase = qtile * 64;
    const int n  = qtile + 1;
    const int n0 = (n + 1) >> 1;
    const int kt0 = half ? n0 : 0;
    const int kt1 = half ? n  : n0;

    auto issue_Q = [&]() {   // no commit; joins caller's group
#pragma unroll
        for (int c = tid; c < 1024; c += 128) {
            int r = c >> 4, c8 = c & 15;
            cp16(smaddr(Qs + r * HS + c8 * 8),
                 Q + (size_t)(qbase + r) * HDIM + c8 * 8);
        }
    };
    auto issue_K = [&](int kbase, int s) {
        __half* Kd = Kb + s * 64 * HS;
#pragma unroll
        for (int c = tid; c < 1024; c += 128) {
            int r = c >> 4, c8 = c & 15;
            cp16(smaddr(Kd + r * HS + c8 * 8),
                 K + (size_t)(kbase + r) * HDIM + c8 * 8);
        }
        cp_commit();
    };
    auto issue_V = [&](int kbase) {
#pragma unroll
        for (int c = tid; c < 1024; c += 128) {
            int r = c >> 4, c8 = c & 15;
            cp16(smaddr(Vb + r * HS + c8 * 8),
                 V + (size_t)(kbase + r) * HDIM + c8 * 8);
        }
        cp_commit();
    };

    float o[16][4];
#pragma unroll
    for (int nt = 0; nt < 16; nt++)
#pragma unroll
        for (int j = 0; j < 4; j++) o[nt][j] = 0.f;
    float mr[2] = {-INFINITY, -INFINITY};
    float lr[2] = {0.f, 0.f};

    if (kt0 < kt1) {
        // ldmatrix per-thread offsets (in halves)
        const int qa_off = (lane & 15) * HS + (lane >> 4) * 8;  // Q A-frag pattern
        const int kq_off = (lane & 7) * HS + (lane >> 3) * 8;   // K B-frag pattern
        const int vv_off = lane * HS;                            // V rows (trans)

        // prologue: group A = {Q, K(kt0)}, group B = {V(kt0)}
        issue_Q();
        issue_K(kt0 * 64, kt0 & 1);
        issue_V(kt0 * 64);
        cp_wait<1>();            // A done (Q + K ready)
        __syncthreads();

        const uint32_t QsA = smaddr(Qs);

        for (int kt = kt0; kt < kt1; kt++) {
            if (kt + 1 < kt1) issue_K((kt + 1) * 64, (kt + 1) & 1);
            else              cp_commit();           // group C

            const uint32_t KsA = smaddr(Kb + (kt & 1) * 64 * HS);
            const uint32_t VsA = smaddr(Vb);

            // -------- S = Q K^T  (16x64 per warp) --------
            float s[8][4];
#pragma unroll
            for (int ni = 0; ni < 8; ni++)
#pragma unroll
                for (int j = 0; j < 4; j++) s[ni][j] = 0.f;

#pragma unroll
            for (int kc = 0; kc < 4; kc++) {
                // Q A-fragments for k = kc*32 .. kc*32+31 (two m16k16 chunks)
                uint32_t qa0[4], qa1[4];
                ldsm4(qa0[0], qa0[1], qa0[2], qa0[3],
                      QsA + (uint32_t)(rb * HS + qa_off + kc * 32) * 2);
                ldsm4(qa1[0], qa1[1], qa1[2], qa1[3],
                      QsA + (uint32_t)(rb * HS + qa_off + kc * 32 + 16) * 2);
#pragma unroll
                for (int ni = 0; ni < 8; ni++) {
                    uint32_t r0, r1, r2, r3;
                    ldsm4(r0, r1, r2, r3,
                          KsA + (uint32_t)(ni * 8 * HS + kq_off + kc * 32) * 2);
                    uint32_t b01[2] = {r0, r1}, b23[2] = {r2, r3};
                    mma16(s[ni], qa0, b01);
                    mma16(s[ni], qa1, b23);
                }
            }

            // -------- causal mask (diagonal tile only) --------
            if (kt == qtile) {
                const int r0l = rb + g, r1l = rb + g + 8;
#pragma unroll
                for (int ni = 0; ni < 8; ni++) {
                    const int c = ni * 8 + 2 * tig;
                    s[ni][0] = (c     <= r0l) ? s[ni][0] : -INFINITY;
                    s[ni][1] = (c + 1 <= r0l) ? s[ni][1] : -INFINITY;
                    s[ni][2] = (c     <= r1l) ? s[ni][2] : -INFINITY;
                    s[ni][3] = (c + 1 <= r1l) ? s[ni][3] : -INFINITY;
                }
            }

            // -------- online softmax (per row-half, quad reduce) --------
#pragma unroll
            for (int h = 0; h < 2; h++) {
                float tm = -INFINITY;
#pragma unroll
                for (int ni = 0; ni < 8; ni++)
                    tm = fmaxf(tm, fmaxf(s[ni][2 * h], s[ni][2 * h + 1]));
                tm = fmaxf(tm, __shfl_xor_sync(0xffffffffu, tm, 1));
                tm = fmaxf(tm, __shfl_xor_sync(0xffffffffu, tm, 2));

                const float mn = fmaxf(mr[h], tm);
                const float alpha = __expf(mr[h] - mn);
                mr[h] = mn;

                float rs = 0.f;
#pragma unroll
                for (int ni = 0; ni < 8; ni++) {
                    float p0 = __expf(s[ni][2 * h]     - mn);
                    float p1 = __expf(s[ni][2 * h + 1] - mn);
                    s[ni][2 * h] = p0; s[ni][2 * h + 1] = p1;
                    rs += p0 + p1;
                }
                rs += __shfl_xor_sync(0xffffffffu, rs, 1);
                rs += __shfl_xor_sync(0xffffffffu, rs, 2);
                lr[h] = lr[h] * alpha + rs;

#pragma unroll
                for (int nt = 0; nt < 16; nt++) {
                    o[nt][2 * h]     *= alpha;
                    o[nt][2 * h + 1] *= alpha;
                }
            }

            // -------- P -> fp16 A-fragments --------
            uint32_t pa[4][4];
#pragma unroll
            for (int js = 0; js < 4; js++) {
                pa[js][0] = ph2(s[2 * js][0],     s[2 * js][1]);
                pa[js][1] = ph2(s[2 * js][2],     s[2 * js][3]);
                pa[js][2] = ph2(s[2 * js + 1][0], s[2 * js + 1][1]);
                pa[js][3] = ph2(s[2 * js + 1][2], s[2 * js + 1][3]);
            }

            // -------- V(kt) ready (group B done; C pending) --------
            cp_wait<1>();
            __syncthreads();

            // -------- O += P V  (16x128 per warp) --------
#pragma unroll
            for (int nt = 0; nt < 16; nt++) {
                const uint32_t base = VsA + (uint32_t)(vv_off + nt * 8) * 2;
#pragma unroll
                for (int kc = 0; kc < 2; kc++) {
                    uint32_t r0, r1, r2, r3;
                    ldsm4t(r0, r1, r2, r3, base + kc * (32 * HS * 2));
                    uint32_t b01[2] = {r0, r1}, b23[2] = {r2, r3};
                    mma16(o[nt], pa[2 * kc],     b01);
                    mma16(o[nt], pa[2 * kc + 1], b23);
                }
            }

            // -------- all warps done reading K(kt)/V(kt) --------
            __syncthreads();
            if (kt + 1 < kt1) issue_V((kt + 1) * 64);
            else              cp_commit();           // group D
            cp_wait<1>();      // C done: K(kt+1) ready; D pending
            __syncthreads();
        }

        cp_wait<0>();
    }

    // -------- epilogue: write partial (o, m, l) --------
    const size_t pidx = ((size_t)(b * NQT + qtile) * 2 + half);
    float* Po = g_Po + pidx * (64 * HDIM);
#pragma unroll
    for (int nt = 0; nt < 16; nt++) {
        const int c = nt * 8 + 2 * tig;
        *(float2*)(Po + (rb + g)     * HDIM + c) = make_float2(o[nt][0], o[nt][1]);
        *(float2*)(Po + (rb + g + 8) * HDIM + c) = make_float2(o[nt][2], o[nt][3]);
    }
    if (tig == 0) {
        g_Pm[pidx * 64 + rb + g]     = mr[0];
        g_Pm[pidx * 64 + rb + g + 8] = mr[1];
        g_Pl[pidx * 64 + rb + g]     = lr[0];
        g_Pl[pidx * 64 + rb + g + 8] = lr[1];
    }
}

// ======================= split-K merge =========================
__global__ __launch_bounds__(256) void merge_kernel(float* __restrict__ Out)
{
    const int q = blockIdx.x, b = blockIdx.y;
    const size_t base = (size_t)(b * NQT + q) * 2;
    const float* o0 = g_Po + base * (64 * HDIM);
    const float* o1 = o0 + 64 * HDIM;

    const int t = threadIdx.x;
    const int r  = t >> 2;            // 64 rows, 4 threads per row
    const int c0 = (t & 3) * 32;      // 32 cols per thread

    const float m0 = g_Pm[base * 64 + r], m1 = g_Pm[(base + 1) * 64 + r];
    const float l0 = g_Pl[base * 64 + r], l1 = g_Pl[(base + 1) * 64 + r];
    const float M  = fmaxf(m0, m1);
    const float w0 = __expf(m0 - M), w1 = __expf(m1 - M);
    const float invL = 1.0f / (l0 * w0 + l1 * w1);

    float* O = Out + (size_t)b * SEQ * HDIM + (size_t)(q * 64 + r) * HDIM;
#pragma unroll
    for (int i = 0; i < 32; i += 4) {
        float4 a = *(const float4*)(o0 + r * HDIM + c0 + i);
        float4 bb = *(const float4*)(o1 + r * HDIM + c0 + i);
        float4 res;
        res.x = (a.x * w0 + bb.x * w1) * invL;
        res.y = (a.y * w0 + bb.y * w1) * invL;
        res.z = (a.z * w0 + bb.z * w1) * invL;
        res.w = (a.w * w0 + bb.w * w1) * invL;
        *(float4*)(O + c0 + i) = res;
    }
}

// =========================== launch =============================
extern "C" void kernel_launch(void* const* d_in, const int* in_sizes, int n_in,
                              void* d_out, int out_size)
{
    (void)in_sizes; (void)n_in; (void)out_size;
    const float* X  = (const float*)d_in[0];
    const float* Wq = (const float*)d_in[1];
    const float* Wk = (const float*)d_in[2];
    const float* Wv = (const float*)d_in[3];
    float* Out = (float*)d_out;

    static int attr_set = 0;
    if (!attr_set) {
        cudaFuncSetAttribute(proj_kernel,
                             cudaFuncAttributeMaxDynamicSharedMemorySize,
                             PROJ_SMEM);
        cudaFuncSetAttribute(attn_kernel,
                             cudaFuncAttributeMaxDynamicSharedMemorySize,
                             ATT_SMEM);
        attr_set = 1;
    }

    // fp32 -> fp16 converts
    convert_X_kernel<<<BSTOT * DDIM / (256 * 8), 256>>>(X);
    dim3 wgrid(DDIM * HDIM / (256 * 8), 3);
    convert_W_kernel<<<wgrid, 256>>>(Wq, Wk, Wv);

    // QKV projections (fp16 tensor cores)
    dim3 pgrid(BSTOT / 128, 3);
    proj_kernel<<<pgrid, 256, PROJ_SMEM>>>();

    // Flash attention, split-K halves
    dim3 agrid(128, NB);
    attn_kernel<<<agrid, 128, ATT_SMEM>>>();

    // Merge halves
    dim3 mgrid(NQT, NB);
    merge_kernel<<<mgrid, 256>>>(Out);
}

// round 10
// speedup vs baseline: 1.0741x; 1.0741x over previous
#include <cuda_runtime.h>
#include <cuda_fp16.h>
#include <math.h>
#include <stdint.h>

// Problem shape (fixed by the dataset)
#define NB      4
#define SEQ     4096
#define DDIM    1024
#define HDIM    128
#define BSTOT   (NB * SEQ)          // 16384 rows
#define NQT     64                  // q-tiles per batch (SEQ/64)

// ---------------- scratch (no cudaMalloc allowed) ----------------
__device__ __half g_Xh[BSTOT * DDIM];       // fp16 X
__device__ __half g_Wh[3 * DDIM * HDIM];    // fp16 Wq|Wk|Wv
__device__ __half g_Qh[BSTOT * HDIM];       // fp16 Q (pre-scaled by 1/sqrt(128))
__device__ __half g_Kh[BSTOT * HDIM];
__device__ __half g_Vh[BSTOT * HDIM];
// split-K partials: [b][qtile][half]{ o:64x128, m:64, l:64 }
__device__ float g_Po[NB * NQT * 2 * 64 * HDIM];
__device__ float g_Pm[NB * NQT * 2 * 64];
__device__ float g_Pl[NB * NQT * 2 * 64];

// ------------------- helpers -------------------
// fp16: D += A(16x16, row) * B(16x8, col), fp32 accum
__device__ __forceinline__ void mma16(float* c, const uint32_t* a, const uint32_t* b) {
    asm volatile("mma.sync.aligned.m16n8k16.row.col.f32.f16.f16.f32 "
        "{%0,%1,%2,%3}, {%4,%5,%6,%7}, {%8,%9}, {%0,%1,%2,%3};"
        : "+f"(c[0]), "+f"(c[1]), "+f"(c[2]), "+f"(c[3])
        : "r"(a[0]), "r"(a[1]), "r"(a[2]), "r"(a[3]), "r"(b[0]), "r"(b[1]));
}
__device__ __forceinline__ void ldsm4(uint32_t& r0, uint32_t& r1, uint32_t& r2, uint32_t& r3,
                                      uint32_t addr) {
    asm volatile("ldmatrix.sync.aligned.m8n8.x4.shared.b16 {%0,%1,%2,%3}, [%4];"
        : "=r"(r0), "=r"(r1), "=r"(r2), "=r"(r3) : "r"(addr));
}
__device__ __forceinline__ void ldsm4t(uint32_t& r0, uint32_t& r1, uint32_t& r2, uint32_t& r3,
                                       uint32_t addr) {
    asm volatile("ldmatrix.sync.aligned.m8n8.x4.trans.shared.b16 {%0,%1,%2,%3}, [%4];"
        : "=r"(r0), "=r"(r1), "=r"(r2), "=r"(r3) : "r"(addr));
}
// pack two f32 -> f16x2 (lo = first element)
__device__ __forceinline__ uint32_t ph2(float lo, float hi) {
    uint32_t r; asm("cvt.rn.f16x2.f32 %0, %1, %2;" : "=r"(r) : "f"(hi), "f"(lo)); return r;
}
__device__ __forceinline__ uint32_t smaddr(const void* p) {
    return (uint32_t)__cvta_generic_to_shared(p);
}
__device__ __forceinline__ void cp16(uint32_t s, const void* g) {
    asm volatile("cp.async.ca.shared.global [%0], [%1], 16;" :: "r"(s), "l"(g));
}
__device__ __forceinline__ void cp_commit() {
    asm volatile("cp.async.commit_group;");
}
template <int N>
__device__ __forceinline__ void cp_wait() {
    asm volatile("cp.async.wait_group %0;" :: "n"(N));
}

// ======================= fp32 -> fp16 converts =========================
__global__ __launch_bounds__(256) void convert_X_kernel(const float* __restrict__ X)
{
    size_t i = ((size_t)blockIdx.x * 256 + threadIdx.x) * 8;
    float4 a = *(const float4*)(X + i);
    float4 b = *(const float4*)(X + i + 4);
    uint4 o;
    o.x = ph2(a.x, a.y); o.y = ph2(a.z, a.w);
    o.z = ph2(b.x, b.y); o.w = ph2(b.z, b.w);
    *(uint4*)(g_Xh + i) = o;
}
__global__ __launch_bounds__(256) void convert_W_kernel(
    const float* __restrict__ Wq, const float* __restrict__ Wk,
    const float* __restrict__ Wv)
{
    const float* W = (blockIdx.y == 0) ? Wq : ((blockIdx.y == 1) ? Wk : Wv);
    size_t i = ((size_t)blockIdx.x * 256 + threadIdx.x) * 8;
    float4 a = *(const float4*)(W + i);
    float4 b = *(const float4*)(W + i + 4);
    uint4 o;
    o.x = ph2(a.x, a.y); o.y = ph2(a.z, a.w);
    o.z = ph2(b.x, b.y); o.w = ph2(b.z, b.w);
    *(uint4*)(g_Wh + (size_t)blockIdx.y * DDIM * HDIM + i) = o;
}

// ======================= QKV projection (fp16) =========================
#define PXS 40
#define PWS 136
#define PROJ_SMEM ((2 * 128 * PXS + 2 * 32 * PWS) * 2)   // 37888 B

__global__ __launch_bounds__(256, 2) void proj_kernel()
{
    const int mat = blockIdx.y;
    const __half* Xg = g_Xh;
    const __half* Wg = g_Wh + (size_t)mat * DDIM * HDIM;
    __half*      Outh = (mat == 0) ? g_Qh : ((mat == 1) ? g_Kh : g_Vh);

    extern __shared__ __half psm[];
    __half* Xb = psm;                      // [2][128*PXS]
    __half* Wb = psm + 2 * 128 * PXS;      // [2][32*PWS]

    const int tid  = threadIdx.x;
    const int warp = tid >> 5, lane = tid & 31;
    const int g = lane >> 2, tig = lane & 3;
    const int wm = warp & 3;
    const int wn = warp >> 2;
    const int row0 = blockIdx.x * 128;

    auto issue_stage = [&](int k0, int s) {
        __half* Xd = Xb + s * 128 * PXS;
        __half* Wd = Wb + s * 32 * PWS;
#pragma unroll
        for (int c = tid; c < 512; c += 256) {
            int r = c >> 2, c8 = c & 3;
            cp16(smaddr(Xd + r * PXS + c8 * 8),
                 Xg + (size_t)(row0 + r) * DDIM + k0 + c8 * 8);
        }
#pragma unroll
        for (int c = tid; c < 512; c += 256) {
            int r = c >> 4, c8 = c & 15;
            cp16(smaddr(Wd + r * PWS + c8 * 8),
                 Wg + (size_t)(k0 + r) * HDIM + c8 * 8);
        }
        cp_commit();
    };

    float acc[2][8][4];
#pragma unroll
    for (int mi = 0; mi < 2; mi++)
#pragma unroll
        for (int ni = 0; ni < 8; ni++)
#pragma unroll
            for (int j = 0; j < 4; j++) acc[mi][ni][j] = 0.f;

    issue_stage(0, 0);

    const int a_off = (lane & 15) * PXS + (lane >> 4) * 8;
    const int b_off = lane * PWS;

    for (int ki = 0; ki < 32; ki++) {
        if (ki < 31) { issue_stage((ki + 1) * 32, (ki + 1) & 1); cp_wait<1>(); }
        else         { cp_wait<0>(); }
        __syncthreads();

        const uint32_t XsA = smaddr(Xb + (ki & 1) * 128 * PXS);
        const uint32_t WsA = smaddr(Wb + (ki & 1) * 32 * PWS);

        uint32_t a[2][2][4];
#pragma unroll
        for (int mi = 0; mi < 2; mi++)
#pragma unroll
            for (int kc = 0; kc < 2; kc++) {
                uint32_t addr = XsA + (uint32_t)((wm * 32 + mi * 16) * PXS + kc * 16 + a_off) * 2;
                ldsm4(a[mi][kc][0], a[mi][kc][1], a[mi][kc][2], a[mi][kc][3], addr);
            }
#pragma unroll
        for (int ni = 0; ni < 8; ni++) {
            uint32_t r0, r1, r2, r3;
            uint32_t addr = WsA + (uint32_t)(b_off + wn * 64 + ni * 8) * 2;
            ldsm4t(r0, r1, r2, r3, addr);
            uint32_t b01[2] = {r0, r1}, b23[2] = {r2, r3};
#pragma unroll
            for (int mi = 0; mi < 2; mi++) {
                mma16(acc[mi][ni], a[mi][0], b01);
                mma16(acc[mi][ni], a[mi][1], b23);
            }
        }
        __syncthreads();
    }

    const float osc = (mat == 0) ? 0.088388347648318447f : 1.0f;
#pragma unroll
    for (int mi = 0; mi < 2; mi++) {
        const int r = row0 + wm * 32 + mi * 16 + g;
#pragma unroll
        for (int ni = 0; ni < 8; ni++) {
            const int c = wn * 64 + ni * 8 + 2 * tig;
            *(uint32_t*)(Outh + (size_t)r       * HDIM + c) =
                ph2(acc[mi][ni][0] * osc, acc[mi][ni][1] * osc);
            *(uint32_t*)(Outh + (size_t)(r + 8) * HDIM + c) =
                ph2(acc[mi][ni][2] * osc, acc[mi][ni][3] * osc);
        }
    }
}

// ======================= flash attention (split-K, pingpong) ==============
// grid (128, NB): bx -> qtile = 63-(bx>>1), half = bx&1.
// Q in registers; K/V triple-buffered stages; S(kt+1)=QK computed BEFORE
// softmax(kt)+PV(kt) so HMMA of next tile overlaps the MUFU/shuffle chain.
#define HS 136                       // half-stride per smem row (272 B)
#define ATT_SMEM (6 * 64 * HS * 2)   // 3 K bufs + 3 V bufs = 104448 B

__global__ __launch_bounds__(128) void attn_kernel()
{
    extern __shared__ __half hsm[];
    __half* Kb = hsm;                  // [3][64*HS]
    __half* Vb = hsm + 3 * 64 * HS;    // [3][64*HS]

    const int tid  = threadIdx.x;
    const int warp = tid >> 5, lane = tid & 31;
    const int g = lane >> 2, tig = lane & 3;
    const int rb = warp * 16;
    const int b  = blockIdx.y;

    const __half* Q = g_Qh + (size_t)b * SEQ * HDIM;
    const __half* K = g_Kh + (size_t)b * SEQ * HDIM;
    const __half* V = g_Vh + (size_t)b * SEQ * HDIM;

    const int qtile = 63 - ((int)blockIdx.x >> 1);   // longest first
    const int half  = (int)blockIdx.x & 1;
    const int qbase = qtile * 64;
    const int n  = qtile + 1;
    const int n0 = (n + 1) >> 1;
    const int kt0 = half ? n0 : 0;
    const int kt1 = half ? n  : n0;

    auto issue_stage = [&](int kbase, int s) {
        __half* Kd = Kb + s * 64 * HS;
        __half* Vd = Vb + s * 64 * HS;
#pragma unroll
        for (int c = tid; c < 1024; c += 128) {
            int r = c >> 4, c8 = c & 15;
            cp16(smaddr(Kd + r * HS + c8 * 8),
                 K + (size_t)(kbase + r) * HDIM + c8 * 8);
            cp16(smaddr(Vd + r * HS + c8 * 8),
                 V + (size_t)(kbase + r) * HDIM + c8 * 8);
        }
        cp_commit();
    };

    float o[16][4];
#pragma unroll
    for (int nt = 0; nt < 16; nt++)
#pragma unroll
        for (int j = 0; j < 4; j++) o[nt][j] = 0.f;
    float mr[2] = {-INFINITY, -INFINITY};
    float lr[2] = {0.f, 0.f};

    if (kt0 < kt1) {
        // Q -> register A-fragments (fp16, pre-scaled in gmem)
        uint32_t qa[8][4];
#pragma unroll
        for (int ks = 0; ks < 8; ks++) {
            const __half* q0 = Q + (size_t)(qbase + rb + g)     * HDIM + ks * 16;
            const __half* q1 = Q + (size_t)(qbase + rb + g + 8) * HDIM + ks * 16;
            qa[ks][0] = *(const uint32_t*)(q0 + 2 * tig);
            qa[ks][1] = *(const uint32_t*)(q1 + 2 * tig);
            qa[ks][2] = *(const uint32_t*)(q0 + 2 * tig + 8);
            qa[ks][3] = *(const uint32_t*)(q1 + 2 * tig + 8);
        }

        // ldmatrix per-thread offsets (in halves)
        const int kq_off = (lane & 7) * HS + (lane >> 3) * 8;
        const int vv_off = lane * HS;

        // S = Q K^T for one tile from K buffer `buf`
        auto qk_tile = [&](float (&s)[8][4], int buf) {
#pragma unroll
            for (int ni = 0; ni < 8; ni++)
#pragma unroll
                for (int j = 0; j < 4; j++) s[ni][j] = 0.f;
            const uint32_t KsA = smaddr(Kb + buf * 64 * HS);
#pragma unroll
            for (int ni = 0; ni < 8; ni++) {
                const uint32_t base = KsA + (uint32_t)(ni * 8 * HS + kq_off) * 2;
#pragma unroll
                for (int kc = 0; kc < 4; kc++) {
                    uint32_t r0, r1, r2, r3;
                    ldsm4(r0, r1, r2, r3, base + kc * 64);
                    uint32_t b01[2] = {r0, r1}, b23[2] = {r2, r3};
                    mma16(s[ni], qa[2 * kc],     b01);
                    mma16(s[ni], qa[2 * kc + 1], b23);
                }
            }
        };

        // mask + online softmax + PV for tile kt (V from buffer kt%3)
        auto process = [&](float (&s)[8][4], int kt) {
            if (kt == qtile) {
                const int r0l = rb + g, r1l = rb + g + 8;
#pragma unroll
                for (int ni = 0; ni < 8; ni++) {
                    const int c = ni * 8 + 2 * tig;
                    s[ni][0] = (c     <= r0l) ? s[ni][0] : -INFINITY;
                    s[ni][1] = (c + 1 <= r0l) ? s[ni][1] : -INFINITY;
                    s[ni][2] = (c     <= r1l) ? s[ni][2] : -INFINITY;
                    s[ni][3] = (c + 1 <= r1l) ? s[ni][3] : -INFINITY;
                }
            }
#pragma unroll
            for (int h = 0; h < 2; h++) {
                float tm = -INFINITY;
#pragma unroll
                for (int ni = 0; ni < 8; ni++)
                    tm = fmaxf(tm, fmaxf(s[ni][2 * h], s[ni][2 * h + 1]));
                tm = fmaxf(tm, __shfl_xor_sync(0xffffffffu, tm, 1));
                tm = fmaxf(tm, __shfl_xor_sync(0xffffffffu, tm, 2));

                const float mn = fmaxf(mr[h], tm);
                const float alpha = __expf(mr[h] - mn);
                mr[h] = mn;

                float rs = 0.f;
#pragma unroll
                for (int ni = 0; ni < 8; ni++) {
                    float p0 = __expf(s[ni][2 * h]     - mn);
                    float p1 = __expf(s[ni][2 * h + 1] - mn);
                    s[ni][2 * h] = p0; s[ni][2 * h + 1] = p1;
                    rs += p0 + p1;
                }
                rs += __shfl_xor_sync(0xffffffffu, rs, 1);
                rs += __shfl_xor_sync(0xffffffffu, rs, 2);
                lr[h] = lr[h] * alpha + rs;

#pragma unroll
                for (int nt = 0; nt < 16; nt++) {
                    o[nt][2 * h]     *= alpha;
                    o[nt][2 * h + 1] *= alpha;
                }
            }

            uint32_t pa[4][4];
#pragma unroll
            for (int js = 0; js < 4; js++) {
                pa[js][0] = ph2(s[2 * js][0],     s[2 * js][1]);
                pa[js][1] = ph2(s[2 * js][2],     s[2 * js][3]);
                pa[js][2] = ph2(s[2 * js + 1][0], s[2 * js + 1][1]);
                pa[js][3] = ph2(s[2 * js + 1][2], s[2 * js + 1][3]);
            }

            const uint32_t VsA = smaddr(Vb + (kt % 3) * 64 * HS);
#pragma unroll
            for (int nt = 0; nt < 16; nt++) {
                const uint32_t base = VsA + (uint32_t)(vv_off + nt * 8) * 2;
#pragma unroll
                for (int kc = 0; kc < 2; kc++) {
                    uint32_t r0, r1, r2, r3;
                    ldsm4t(r0, r1, r2, r3, base + kc * (32 * HS * 2));
                    uint32_t b01[2] = {r0, r1}, b23[2] = {r2, r3};
                    mma16(o[nt], pa[2 * kc],     b01);
                    mma16(o[nt], pa[2 * kc + 1], b23);
                }
            }
        };

        // prologue: stages kt0, kt0+1 in flight; compute S(kt0)
        issue_stage(kt0 * 64, kt0 % 3);
        if (kt0 + 1 < kt1) issue_stage((kt0 + 1) * 64, (kt0 + 1) % 3);
        else               cp_commit();
        cp_wait<1>();          // stage kt0 ready
        __syncthreads();

        float s1[8][4], s2[8][4];
        qk_tile(s1, kt0 % 3);

        int kt = kt0;
        while (true) {
            // ---- iteration with cur = s1, next into s2 ----
            if (kt + 1 < kt1) {
                if (kt + 2 < kt1) issue_stage((kt + 2) * 64, (kt + 2) % 3);
                else              cp_commit();
                cp_wait<1>();      // stage kt+1 ready
                __syncthreads();
                qk_tile(s2, (kt + 1) % 3);   // overlaps with process(s1) below
            }
            process(s1, kt);
            __syncthreads();
            if (++kt >= kt1) break;

            // ---- iteration with cur = s2, next into s1 ----
            if (kt + 1 < kt1) {
                if (kt + 2 < kt1) issue_stage((kt + 2) * 64, (kt + 2) % 3);
                else              cp_commit();
                cp_wait<1>();
                __syncthreads();
                qk_tile(s1, (kt + 1) % 3);
            }
            process(s2, kt);
            __syncthreads();
            if (++kt >= kt1) break;
        }

        cp_wait<0>();
    }

    // -------- epilogue: write partial (o, m, l) --------
    const size_t pidx = ((size_t)(b * NQT + qtile) * 2 + half);
    float* Po = g_Po + pidx * (64 * HDIM);
#pragma unroll
    for (int nt = 0; nt < 16; nt++) {
        const int c = nt * 8 + 2 * tig;
        *(float2*)(Po + (rb + g)     * HDIM + c) = make_float2(o[nt][0], o[nt][1]);
        *(float2*)(Po + (rb + g + 8) * HDIM + c) = make_float2(o[nt][2], o[nt][3]);
    }
    if (tig == 0) {
        g_Pm[pidx * 64 + rb + g]     = mr[0];
        g_Pm[pidx * 64 + rb + g + 8] = mr[1];
        g_Pl[pidx * 64 + rb + g]     = lr[0];
        g_Pl[pidx * 64 + rb + g + 8] = lr[1];
    }
}

// ======================= split-K merge =========================
__global__ __launch_bounds__(256) void merge_kernel(float* __restrict__ Out)
{
    const int q = blockIdx.x, b = blockIdx.y;
    const size_t base = (size_t)(b * NQT + q) * 2;
    const float* o0 = g_Po + base * (64 * HDIM);
    const float* o1 = o0 + 64 * HDIM;

    const int t = threadIdx.x;
    const int r  = t >> 2;            // 64 rows, 4 threads per row
    const int c0 = (t & 3) * 32;      // 32 cols per thread

    const float m0 = g_Pm[base * 64 + r], m1 = g_Pm[(base + 1) * 64 + r];
    const float l0 = g_Pl[base * 64 + r], l1 = g_Pl[(base + 1) * 64 + r];
    const float M  = fmaxf(m0, m1);
    const float w0 = __expf(m0 - M), w1 = __expf(m1 - M);
    const float invL = 1.0f / (l0 * w0 + l1 * w1);

    float* O = Out + (size_t)b * SEQ * HDIM + (size_t)(q * 64 + r) * HDIM;
#pragma unroll
    for (int i = 0; i < 32; i += 4) {
        float4 a = *(const float4*)(o0 + r * HDIM + c0 + i);
        float4 bb = *(const float4*)(o1 + r * HDIM + c0 + i);
        float4 res;
        res.x = (a.x * w0 + bb.x * w1) * invL;
        res.y = (a.y * w0 + bb.y * w1) * invL;
        res.z = (a.z * w0 + bb.z * w1) * invL;
        res.w = (a.w * w0 + bb.w * w1) * invL;
        *(float4*)(O + c0 + i) = res;
    }
}

// =========================== launch =============================
extern "C" void kernel_launch(void* const* d_in, const int* in_sizes, int n_in,
                              void* d_out, int out_size)
{
    (void)in_sizes; (void)n_in; (void)out_size;
    const float* X  = (const float*)d_in[0];
    const float* Wq = (const float*)d_in[1];
    const float* Wk = (const float*)d_in[2];
    const float* Wv = (const float*)d_in[3];
    float* Out = (float*)d_out;

    static int attr_set = 0;
    if (!attr_set) {
        cudaFuncSetAttribute(proj_kernel,
                             cudaFuncAttributeMaxDynamicSharedMemorySize,
                             PROJ_SMEM);
        cudaFuncSetAttribute(attn_kernel,
                             cudaFuncAttributeMaxDynamicSharedMemorySize,
                             ATT_SMEM);
        attr_set = 1;
    }

    // fp32 -> fp16 converts
    convert_X_kernel<<<BSTOT * DDIM / (256 * 8), 256>>>(X);
    dim3 wgrid(DDIM * HDIM / (256 * 8), 3);
    convert_W_kernel<<<wgrid, 256>>>(Wq, Wk, Wv);

    // QKV projections (fp16 tensor cores)
    dim3 pgrid(BSTOT / 128, 3);
    proj_kernel<<<pgrid, 256, PROJ_SMEM>>>();

    // Flash attention, split-K halves (pingpong mainloop)
    dim3 agrid(128, NB);
    attn_kernel<<<agrid, 128, ATT_SMEM>>>();

    // Merge halves
    dim3 mgrid(NQT, NB);
    merge_kernel<<<mgrid, 256>>>(Out);
}

// round 11
// speedup vs baseline: 1.0889x; 1.0138x over previous
#include <cuda_runtime.h>
#include <cuda_fp16.h>
#include <math.h>
#include <stdint.h>

// Problem shape (fixed by the dataset)
#define NB      4
#define SEQ     4096
#define DDIM    1024
#define HDIM    128
#define BSTOT   (NB * SEQ)          // 16384 rows
#define NQT     64                  // q-tiles per batch (SEQ/64)

// ---------------- scratch (no cudaMalloc allowed) ----------------
__device__ __half g_Wh[3 * DDIM * HDIM];    // fp16 Wq|Wk|Wv
__device__ __half g_Qh[BSTOT * HDIM];       // fp16 Q (pre-scaled by log2e/sqrt(128))
__device__ __half g_Kh[BSTOT * HDIM];
__device__ __half g_Vh[BSTOT * HDIM];
// split-K partials: [b][qtile][half]{ o:64x128, m:64, l:64 }  (m in log2 domain)
__device__ float g_Po[NB * NQT * 2 * 64 * HDIM];
__device__ float g_Pm[NB * NQT * 2 * 64];
__device__ float g_Pl[NB * NQT * 2 * 64];

// ------------------- helpers -------------------
// fp16: D += A(16x16, row) * B(16x8, col), fp32 accum
__device__ __forceinline__ void mma16(float* c, const uint32_t* a, const uint32_t* b) {
    asm volatile("mma.sync.aligned.m16n8k16.row.col.f32.f16.f16.f32 "
        "{%0,%1,%2,%3}, {%4,%5,%6,%7}, {%8,%9}, {%0,%1,%2,%3};"
        : "+f"(c[0]), "+f"(c[1]), "+f"(c[2]), "+f"(c[3])
        : "r"(a[0]), "r"(a[1]), "r"(a[2]), "r"(a[3]), "r"(b[0]), "r"(b[1]));
}
__device__ __forceinline__ void ldsm4(uint32_t& r0, uint32_t& r1, uint32_t& r2, uint32_t& r3,
                                      uint32_t addr) {
    asm volatile("ldmatrix.sync.aligned.m8n8.x4.shared.b16 {%0,%1,%2,%3}, [%4];"
        : "=r"(r0), "=r"(r1), "=r"(r2), "=r"(r3) : "r"(addr));
}
__device__ __forceinline__ void ldsm4t(uint32_t& r0, uint32_t& r1, uint32_t& r2, uint32_t& r3,
                                       uint32_t addr) {
    asm volatile("ldmatrix.sync.aligned.m8n8.x4.trans.shared.b16 {%0,%1,%2,%3}, [%4];"
        : "=r"(r0), "=r"(r1), "=r"(r2), "=r"(r3) : "r"(addr));
}
// pack two f32 -> f16x2 (lo = first element)
__device__ __forceinline__ uint32_t ph2(float lo, float hi) {
    uint32_t r; asm("cvt.rn.f16x2.f32 %0, %1, %2;" : "=r"(r) : "f"(hi), "f"(lo)); return r;
}
// 2^x, single MUFU op (exp done in log2 domain)
__device__ __forceinline__ float ex2(float x) {
    float r; asm("ex2.approx.ftz.f32 %0, %1;" : "=f"(r) : "f"(x)); return r;
}
__device__ __forceinline__ uint32_t smaddr(const void* p) {
    return (uint32_t)__cvta_generic_to_shared(p);
}
__device__ __forceinline__ void cp16(uint32_t s, const void* g) {
    asm volatile("cp.async.ca.shared.global [%0], [%1], 16;" :: "r"(s), "l"(g));
}
__device__ __forceinline__ void cp_commit() {
    asm volatile("cp.async.commit_group;");
}
template <int N>
__device__ __forceinline__ void cp_wait() {
    asm volatile("cp.async.wait_group %0;" :: "n"(N));
}

// ======================= W fp32 -> fp16 =========================
__global__ __launch_bounds__(256) void convert_W_kernel(
    const float* __restrict__ Wq, const float* __restrict__ Wk,
    const float* __restrict__ Wv)
{
    const float* W = (blockIdx.y == 0) ? Wq : ((blockIdx.y == 1) ? Wk : Wv);
    size_t i = ((size_t)blockIdx.x * 256 + threadIdx.x) * 8;
    float4 a = *(const float4*)(W + i);
    float4 b = *(const float4*)(W + i + 4);
    uint4 o;
    o.x = ph2(a.x, a.y); o.y = ph2(a.z, a.w);
    o.z = ph2(b.x, b.y); o.w = ph2(b.z, b.w);
    *(uint4*)(g_Wh + (size_t)blockIdx.y * DDIM * HDIM + i) = o;
}

// ======================= fused QKV projection =========================
// [Q|K|V][64 rows, 384 cols] = X[64,1024] (fp32, converted in-kernel) @ Wh[1024,384].
// 512 thr = 16 warps: wm=warp&3 (16 rows), wn=warp>>2 (96 cols = 12 n-tiles).
#define FXS 40    // X fp16 smem stride (halves)
#define FWS 392   // W fp16 smem stride (halves); 392 % 32 banks == proven-conflict-free class
#define FUSED_SMEM ((2 * 64 * FXS + 2 * 32 * FWS) * 2)   // 60416 B

__global__ __launch_bounds__(512) void fused_proj_kernel(const float* __restrict__ X)
{
    extern __shared__ __half fsm[];
    __half* Xb = fsm;                    // [2][64*FXS]
    __half* Wb = fsm + 2 * 64 * FXS;     // [2][32*FWS]

    const int tid  = threadIdx.x;
    const int warp = tid >> 5, lane = tid & 31;
    const int g = lane >> 2, tig = lane & 3;
    const int wm = warp & 3;      // 4 M-groups x 16 rows
    const int wn = warp >> 2;     // 4 N-groups x 96 cols
    const int row0 = blockIdx.x * 64;

    // W stage via cp.async (one commit group per stage)
    auto issue_W = [&](int k0, int s) {
        __half* Wd = Wb + s * 32 * FWS;
#pragma unroll
        for (int c = tid; c < 1536; c += 512) {     // 32 rows x 48 chunks of 8 halves
            int r = c / 48, cc = c % 48;
            int mat = cc >> 4, col = (cc & 15) * 8;
            cp16(smaddr(Wd + r * FWS + cc * 8),
                 g_Wh + (size_t)mat * DDIM * HDIM + (size_t)(k0 + r) * HDIM + col);
        }
        cp_commit();
    };

    // X staging: one float4 per thread per stage (64 rows x 32 cols)
    const int xr = tid >> 3, xc = (tid & 7) * 4;

    float acc[12][4];
#pragma unroll
    for (int nt = 0; nt < 12; nt++)
#pragma unroll
        for (int j = 0; j < 4; j++) acc[nt][j] = 0.f;

    float4 xreg = *(const float4*)(X + (size_t)(row0 + xr) * DDIM + xc);
    issue_W(0, 0);

    const int a_off = (lane & 15) * FXS + (lane >> 4) * 8;
    const int b_off = lane * FWS;

    for (int ki = 0; ki < 32; ki++) {
        {   // store prefetched X tile (cvt fp32->fp16) into buf ki&1
            uint2 p; p.x = ph2(xreg.x, xreg.y); p.y = ph2(xreg.z, xreg.w);
            *(uint2*)(Xb + (ki & 1) * 64 * FXS + xr * FXS + xc) = p;
        }
        if (ki < 31) {
            xreg = *(const float4*)(X + (size_t)(row0 + xr) * DDIM + (ki + 1) * 32 + xc);
            issue_W((ki + 1) * 32, (ki + 1) & 1);
            cp_wait<1>();
        } else {
            cp_wait<0>();
        }
        __syncthreads();

        const uint32_t XsA = smaddr(Xb + (ki & 1) * 64 * FXS);
        const uint32_t WsA = smaddr(Wb + (ki & 1) * 32 * FWS);

        uint32_t a0[4], a1[4];
        ldsm4(a0[0], a0[1], a0[2], a0[3], XsA + (uint32_t)(wm * 16 * FXS + a_off) * 2);
        ldsm4(a1[0], a1[1], a1[2], a1[3], XsA + (uint32_t)(wm * 16 * FXS + a_off + 16) * 2);
#pragma unroll
        for (int nt = 0; nt < 12; nt++) {
            uint32_t r0, r1, r2, r3;
            ldsm4t(r0, r1, r2, r3, WsA + (uint32_t)(b_off + wn * 96 + nt * 8) * 2);
            uint32_t b01[2] = {r0, r1}, b23[2] = {r2, r3};
            mma16(acc[nt], a0, b01);
            mma16(acc[nt], a1, b23);
        }
        __syncthreads();
    }

    // epilogue: route each n-tile to Q/K/V; Q pre-scaled into log2 domain
    const float qsc = 0.088388347648318447f * 1.4426950408889634f;
    const int r = row0 + wm * 16 + g;
#pragma unroll
    for (int nt = 0; nt < 12; nt++) {
        const int ncol = wn * 96 + nt * 8 + 2 * tig;
        const int mat = ncol >> 7, col = ncol & 127;
        __half* Outh = (mat == 0) ? g_Qh : ((mat == 1) ? g_Kh : g_Vh);
        const float sc = (mat == 0) ? qsc : 1.0f;
        *(uint32_t*)(Outh + (size_t)r       * HDIM + col) = ph2(acc[nt][0] * sc, acc[nt][1] * sc);
        *(uint32_t*)(Outh + (size_t)(r + 8) * HDIM + col) = ph2(acc[nt][2] * sc, acc[nt][3] * sc);
    }
}

// ======================= flash attention (split-K) ========================
// grid (128, NB): bx -> qtile = 63-(bx>>1), half = bx&1.
// R8 structure (Q in regs, K+V joint double-buffered stages, 2-deep prefetch);
// launch_bounds(128,3) for 3 CTAs/SM; softmax in log2 domain (single EX2).
#define HS 136                       // half-stride per smem row (272 B)
#define ATT_SMEM (4 * 64 * HS * 2)   // 2 K bufs + 2 V bufs = 69632 B

__global__ __launch_bounds__(128, 3) void attn_kernel()
{
    extern __shared__ __half hsm[];
    __half* Kb = hsm;                  // [2][64*HS]
    __half* Vb = hsm + 2 * 64 * HS;    // [2][64*HS]

    const int tid  = threadIdx.x;
    const int warp = tid >> 5, lane = tid & 31;
    const int g = lane >> 2, tig = lane & 3;
    const int rb = warp * 16;
    const int b  = blockIdx.y;

    const __half* Q = g_Qh + (size_t)b * SEQ * HDIM;
    const __half* K = g_Kh + (size_t)b * SEQ * HDIM;
    const __half* V = g_Vh + (size_t)b * SEQ * HDIM;

    const int qtile = 63 - ((int)blockIdx.x >> 1);   // longest first
    const int half  = (int)blockIdx.x & 1;
    const int qbase = qtile * 64;
    const int n  = qtile + 1;
    const int n0 = (n + 1) >> 1;
    const int kt0 = half ? n0 : 0;
    const int kt1 = half ? n  : n0;

    auto issue_stage = [&](int kbase, int s) {
        __half* Kd = Kb + s * 64 * HS;
        __half* Vd = Vb + s * 64 * HS;
#pragma unroll
        for (int c = tid; c < 1024; c += 128) {
            int r = c >> 4, c8 = c & 15;
            cp16(smaddr(Kd + r * HS + c8 * 8),
                 K + (size_t)(kbase + r) * HDIM + c8 * 8);
            cp16(smaddr(Vd + r * HS + c8 * 8),
                 V + (size_t)(kbase + r) * HDIM + c8 * 8);
        }
        cp_commit();
    };

    float o[16][4];
#pragma unroll
    for (int nt = 0; nt < 16; nt++)
#pragma unroll
        for (int j = 0; j < 4; j++) o[nt][j] = 0.f;
    float mr[2] = {-INFINITY, -INFINITY};
    float lr[2] = {0.f, 0.f};

    if (kt0 < kt1) {
        // Q -> register A-fragments (fp16, log2-prescaled in gmem)
        uint32_t qa[8][4];
#pragma unroll
        for (int ks = 0; ks < 8; ks++) {
            const __half* q0 = Q + (size_t)(qbase + rb + g)     * HDIM + ks * 16;
            const __half* q1 = Q + (size_t)(qbase + rb + g + 8) * HDIM + ks * 16;
            qa[ks][0] = *(const uint32_t*)(q0 + 2 * tig);
            qa[ks][1] = *(const uint32_t*)(q1 + 2 * tig);
            qa[ks][2] = *(const uint32_t*)(q0 + 2 * tig + 8);
            qa[ks][3] = *(const uint32_t*)(q1 + 2 * tig + 8);
        }

        // ldmatrix per-thread offsets (in halves)
        const int kq_off = (lane & 7) * HS + (lane >> 3) * 8;
        const int vv_off = lane * HS;

        // prologue: 2-deep prefetch
        issue_stage(kt0 * 64, kt0 & 1);
        if (kt0 + 1 < kt1) issue_stage((kt0 + 1) * 64, (kt0 + 1) & 1);
        else               cp_commit();

        for (int kt = kt0; kt < kt1; kt++) {
            cp_wait<1>();          // stage kt arrived
            __syncthreads();

            const uint32_t KsA = smaddr(Kb + (kt & 1) * 64 * HS);
            const uint32_t VsA = smaddr(Vb + (kt & 1) * 64 * HS);

            // -------- S = Q K^T  (16x64 per warp; log2-domain scores) --------
            float s[8][4];
#pragma unroll
            for (int ni = 0; ni < 8; ni++)
#pragma unroll
                for (int j = 0; j < 4; j++) s[ni][j] = 0.f;

#pragma unroll
            for (int ni = 0; ni < 8; ni++) {
                const uint32_t base = KsA + (uint32_t)(ni * 8 * HS + kq_off) * 2;
#pragma unroll
                for (int kc = 0; kc < 4; kc++) {
                    uint32_t r0, r1, r2, r3;
                    ldsm4(r0, r1, r2, r3, base + kc * 64);
                    uint32_t b01[2] = {r0, r1}, b23[2] = {r2, r3};
                    mma16(s[ni], qa[2 * kc],     b01);
                    mma16(s[ni], qa[2 * kc + 1], b23);
                }
            }

            // -------- causal mask (diagonal tile only) --------
            if (kt == qtile) {
                const int r0l = rb + g, r1l = rb + g + 8;
#pragma unroll
                for (int ni = 0; ni < 8; ni++) {
                    const int c = ni * 8 + 2 * tig;
                    s[ni][0] = (c     <= r0l) ? s[ni][0] : -INFINITY;
                    s[ni][1] = (c + 1 <= r0l) ? s[ni][1] : -INFINITY;
                    s[ni][2] = (c     <= r1l) ? s[ni][2] : -INFINITY;
                    s[ni][3] = (c + 1 <= r1l) ? s[ni][3] : -INFINITY;
                }
            }

            // -------- online softmax (log2 domain, single EX2 per element) ----
#pragma unroll
            for (int h = 0; h < 2; h++) {
                float tm = -INFINITY;
#pragma unroll
                for (int ni = 0; ni < 8; ni++)
                    tm = fmaxf(tm, fmaxf(s[ni][2 * h], s[ni][2 * h + 1]));
                tm = fmaxf(tm, __shfl_xor_sync(0xffffffffu, tm, 1));
                tm = fmaxf(tm, __shfl_xor_sync(0xffffffffu, tm, 2));

                const float mn = fmaxf(mr[h], tm);
                const float alpha = ex2(mr[h] - mn);
                mr[h] = mn;

                float rs = 0.f;
#pragma unroll
                for (int ni = 0; ni < 8; ni++) {
                    float p0 = ex2(s[ni][2 * h]     - mn);
                    float p1 = ex2(s[ni][2 * h + 1] - mn);
                    s[ni][2 * h] = p0; s[ni][2 * h + 1] = p1;
                    rs += p0 + p1;
                }
                rs += __shfl_xor_sync(0xffffffffu, rs, 1);
                rs += __shfl_xor_sync(0xffffffffu, rs, 2);
                lr[h] = lr[h] * alpha + rs;

#pragma unroll
                for (int nt = 0; nt < 16; nt++) {
                    o[nt][2 * h]     *= alpha;
                    o[nt][2 * h + 1] *= alpha;
                }
            }

            // -------- P -> fp16 A-fragments --------
            uint32_t pa[4][4];
#pragma unroll
            for (int js = 0; js < 4; js++) {
                pa[js][0] = ph2(s[2 * js][0],     s[2 * js][1]);
                pa[js][1] = ph2(s[2 * js][2],     s[2 * js][3]);
                pa[js][2] = ph2(s[2 * js + 1][0], s[2 * js + 1][1]);
                pa[js][3] = ph2(s[2 * js + 1][2], s[2 * js + 1][3]);
            }

            // -------- O += P V  (16x128 per warp) --------
#pragma unroll
            for (int nt = 0; nt < 16; nt++) {
                const uint32_t base = VsA + (uint32_t)(vv_off + nt * 8) * 2;
#pragma unroll
                for (int kc = 0; kc < 2; kc++) {
                    uint32_t r0, r1, r2, r3;
                    ldsm4t(r0, r1, r2, r3, base + kc * (32 * HS * 2));
                    uint32_t b01[2] = {r0, r1}, b23[2] = {r2, r3};
                    mma16(o[nt], pa[2 * kc],     b01);
                    mma16(o[nt], pa[2 * kc + 1], b23);
                }
            }

            // -------- all warps done reading stage kt; refill its buffer ------
            __syncthreads();
            if (kt + 2 < kt1) issue_stage((kt + 2) * 64, kt & 1);
            else              cp_commit();    // keep wait<1> invariant exact
        }

        cp_wait<0>();
    }

    // -------- epilogue: write partial (o, m, l); m in log2 domain --------
    const size_t pidx = ((size_t)(b * NQT + qtile) * 2 + half);
    float* Po = g_Po + pidx * (64 * HDIM);
#pragma unroll
    for (int nt = 0; nt < 16; nt++) {
        const int c = nt * 8 + 2 * tig;
        *(float2*)(Po + (rb + g)     * HDIM + c) = make_float2(o[nt][0], o[nt][1]);
        *(float2*)(Po + (rb + g + 8) * HDIM + c) = make_float2(o[nt][2], o[nt][3]);
    }
    if (tig == 0) {
        g_Pm[pidx * 64 + rb + g]     = mr[0];
        g_Pm[pidx * 64 + rb + g + 8] = mr[1];
        g_Pl[pidx * 64 + rb + g]     = lr[0];
        g_Pl[pidx * 64 + rb + g + 8] = lr[1];
    }
}

// ======================= split-K merge =========================
__global__ __launch_bounds__(256) void merge_kernel(float* __restrict__ Out)
{
    const int q = blockIdx.x, b = blockIdx.y;
    const size_t base = (size_t)(b * NQT + q) * 2;
    const float* o0 = g_Po + base * (64 * HDIM);
    const float* o1 = o0 + 64 * HDIM;

    const int t = threadIdx.x;
    const int r  = t >> 2;            // 64 rows, 4 threads per row
    const int c0 = (t & 3) * 32;      // 32 cols per thread

    const float m0 = g_Pm[base * 64 + r], m1 = g_Pm[(base + 1) * 64 + r];
    const float l0 = g_Pl[base * 64 + r], l1 = g_Pl[(base + 1) * 64 + r];
    const float M  = fmaxf(m0, m1);
    const float w0 = ex2(m0 - M), w1 = ex2(m1 - M);   // log2-domain maxima
    const float invL = 1.0f / (l0 * w0 + l1 * w1);

    float* O = Out + (size_t)b * SEQ * HDIM + (size_t)(q * 64 + r) * HDIM;
#pragma unroll
    for (int i = 0; i < 32; i += 4) {
        float4 a = *(const float4*)(o0 + r * HDIM + c0 + i);
        float4 bb = *(const float4*)(o1 + r * HDIM + c0 + i);
        float4 res;
        res.x = (a.x * w0 + bb.x * w1) * invL;
        res.y = (a.y * w0 + bb.y * w1) * invL;
        res.z = (a.z * w0 + bb.z * w1) * invL;
        res.w = (a.w * w0 + bb.w * w1) * invL;
        *(float4*)(O + c0 + i) = res;
    }
}

// =========================== launch =============================
extern "C" void kernel_launch(void* const* d_in, const int* in_sizes, int n_in,
                              void* d_out, int out_size)
{
    (void)in_sizes; (void)n_in; (void)out_size;
    const float* X  = (const float*)d_in[0];
    const float* Wq = (const float*)d_in[1];
    const float* Wk = (const float*)d_in[2];
    const float* Wv = (const float*)d_in[3];
    float* Out = (float*)d_out;

    static int attr_set = 0;
    if (!attr_set) {
        cudaFuncSetAttribute(fused_proj_kernel,
                             cudaFuncAttributeMaxDynamicSharedMemorySize,
                             FUSED_SMEM);
        cudaFuncSetAttribute(attn_kernel,
                             cudaFuncAttributeMaxDynamicSharedMemorySize,
                             ATT_SMEM);
        attr_set = 1;
    }

    // W fp32 -> fp16 (concat layout)
    dim3 wgrid(DDIM * HDIM / (256 * 8), 3);
    convert_W_kernel<<<wgrid, 256>>>(Wq, Wk, Wv);

    // Fused QKV projection (reads fp32 X once)
    fused_proj_kernel<<<BSTOT / 64, 512, FUSED_SMEM>>>(X);

    // Flash attention, split-K halves
    dim3 agrid(128, NB);
    attn_kernel<<<agrid, 128, ATT_SMEM>>>();

    // Merge halves
    dim3 mgrid(NQT, NB);
    merge_kernel<<<mgrid, 256>>>(Out);
}